// round 1
// baseline (speedup 1.0000x reference)
#include <cuda_runtime.h>

// SessionSpatialProjector: out[b,s,t] = sum_c W[sid[b],s,c] * x[b,c,t] + bias[sid[b],s]
// with out[b,s,t] = 0 for t >= seq_len[b].
// Shapes: x [64,128,4096] f32, W [8,256,128] f32, b [8,256] f32,
//         sid/ccount/slen [64] i32, out [64,256,4096] f32.

#define B_DIM 64
#define MAX_C 128
#define MAX_T 4096
#define NSRC  256

#define BS 128   // S tile
#define BT 128   // T tile
#define BK 16    // K chunk
#define WS_STRIDE 132  // padded to kill STS bank conflicts, keeps 16B alignment (528B rows)

__global__ __launch_bounds__(256, 2)
void ssp_kernel(const float* __restrict__ x,
                const float* __restrict__ W,
                const float* __restrict__ bias,
                const int*   __restrict__ sid,
                const int*   __restrict__ ccount,
                const int*   __restrict__ seqlen,
                float*       __restrict__ out)
{
    __shared__ float Ws[BK][WS_STRIDE];  // [k][s]  (W tile transposed)
    __shared__ float Xs[BK][BT];         // [k][t]

    const int b   = blockIdx.z;
    const int s0  = blockIdx.y * BS;
    const int t0  = blockIdx.x * BT;
    const int tid = threadIdx.x;
    const int tx  = tid & 15;   // t direction (16)
    const int ty  = tid >> 4;   // s direction (16)

    const int slen = seqlen[b];
    float* outb = out + ((size_t)b * NSRC + s0) * MAX_T + t0;

    // Fully-masked tile: just write zeros (output buffer is poisoned).
    if (t0 >= slen) {
        #pragma unroll 4
        for (int i = tid; i < (BS * BT) / 4; i += 256) {
            int row = i >> 5;        // BT/4 = 32 float4 per row
            int col = i & 31;
            *(float4*)(outb + (size_t)row * MAX_T + col * 4) = make_float4(0.f, 0.f, 0.f, 0.f);
        }
        return;
    }

    const int session = sid[b];
    const int cc      = ccount[b];
    const int kmax    = ((cc + BK - 1) / BK) * BK;   // W/x are exactly zero beyond cc

    const float* Wb = W + ((size_t)session * NSRC + s0) * MAX_C;
    const float* xb = x + (size_t)b * MAX_C * MAX_T + t0;

    float acc[8][8];
    #pragma unroll
    for (int i = 0; i < 8; i++)
        #pragma unroll
        for (int j = 0; j < 8; j++)
            acc[i][j] = 0.f;

    for (int k0 = 0; k0 < kmax; k0 += BK) {
        // --- Load W tile [BS x BK] into Ws transposed [k][s] ---
        // 128 rows * 4 float4/row = 512 float4, 2 per thread.
        #pragma unroll
        for (int i = 0; i < 2; i++) {
            int idx = tid + i * 256;      // 0..511
            int row = idx >> 2;           // 0..127 (s within tile)
            int c4  = idx & 3;            // which float4 along k
            float4 w4 = *(const float4*)(Wb + (size_t)row * MAX_C + k0 + c4 * 4);
            Ws[c4 * 4 + 0][row] = w4.x;
            Ws[c4 * 4 + 1][row] = w4.y;
            Ws[c4 * 4 + 2][row] = w4.z;
            Ws[c4 * 4 + 3][row] = w4.w;
        }
        // --- Load x tile [BK x BT] into Xs [k][t] (coalesced along t) ---
        // 16*128 floats = 512 float4, 2 per thread.
        #pragma unroll
        for (int i = 0; i < 2; i++) {
            int idx = tid + i * 256;
            int kr  = idx >> 5;           // 0..15
            int t4  = idx & 31;           // float4 along t
            *(float4*)&Xs[kr][t4 * 4] =
                *(const float4*)(xb + (size_t)(k0 + kr) * MAX_T + t4 * 4);
        }
        __syncthreads();

        #pragma unroll
        for (int k = 0; k < BK; k++) {
            float a[8], bv[8];
            *(float4*)&a[0]  = *(const float4*)&Ws[k][ty * 8];
            *(float4*)&a[4]  = *(const float4*)&Ws[k][ty * 8 + 4];
            *(float4*)&bv[0] = *(const float4*)&Xs[k][tx * 8];
            *(float4*)&bv[4] = *(const float4*)&Xs[k][tx * 8 + 4];
            #pragma unroll
            for (int i = 0; i < 8; i++)
                #pragma unroll
                for (int j = 0; j < 8; j++)
                    acc[i][j] = fmaf(a[i], bv[j], acc[i][j]);
        }
        __syncthreads();
    }

    // --- Epilogue: add bias, apply seq_len mask, store ---
    const float* biasb = bias + session * NSRC + s0;
    const int tbase = t0 + tx * 8;
    #pragma unroll
    for (int i = 0; i < 8; i++) {
        float bvs = biasb[ty * 8 + i];
        float* orow = outb + (size_t)(ty * 8 + i) * MAX_T + tx * 8;
        #pragma unroll
        for (int j = 0; j < 8; j += 4) {
            float4 v;
            v.x = (tbase + j + 0 < slen) ? acc[i][j + 0] + bvs : 0.f;
            v.y = (tbase + j + 1 < slen) ? acc[i][j + 1] + bvs : 0.f;
            v.z = (tbase + j + 2 < slen) ? acc[i][j + 2] + bvs : 0.f;
            v.w = (tbase + j + 3 < slen) ? acc[i][j + 3] + bvs : 0.f;
            *(float4*)(orow + j) = v;
        }
    }
}

extern "C" void kernel_launch(void* const* d_in, const int* in_sizes, int n_in,
                              void* d_out, int out_size)
{
    const float* x      = (const float*)d_in[0];
    const float* W      = (const float*)d_in[1];
    const float* bias   = (const float*)d_in[2];
    const int*   sid    = (const int*)d_in[3];
    const int*   ccount = (const int*)d_in[4];
    const int*   slen   = (const int*)d_in[5];
    float* out = (float*)d_out;

    dim3 grid(MAX_T / BT, NSRC / BS, B_DIM);   // (32, 2, 64)
    ssp_kernel<<<grid, 256>>>(x, W, bias, sid, ccount, slen, out);
}

// round 3
// speedup vs baseline: 2.2879x; 2.2879x over previous
#include <cuda_runtime.h>
#include <cstdint>

// SessionSpatialProjector via mma.sync tf32 tensor cores (compute_100-safe PTX).
// out[b,s,t] = sum_c W[sid[b],s,c] * x[b,c,t] + bias[sid[b],s]; 0 for t >= seq_len[b].
// x [64,128,4096] f32, W [8,256,128] f32, bias [8,256] f32, out [64,256,4096] f32.

#define BB   64
#define CMAX 128
#define TT   4096
#define SS   256

#define TILE_S 128
#define TILE_T 128
#define WS_STR 132      // W smem row stride (floats): bank = (4s+k)%32, conflict-free
#define XS_STR 136      // x smem row stride (floats): bank = (8k+t)%32, conflict-free
#define XBUF   (32 * XS_STR)

static __device__ __forceinline__ uint32_t f2tf32(float f) {
    uint32_t u; asm("cvt.rna.tf32.f32 %0, %1;" : "=r"(u) : "f"(f)); return u;
}
static __device__ __forceinline__ uint32_t smem_u32(const void* p) {
    uint32_t a;
    asm("{ .reg .u64 t; cvta.to.shared.u64 t, %1; cvt.u32.u64 %0, t; }" : "=r"(a) : "l"(p));
    return a;
}
static __device__ __forceinline__ void cp16(uint32_t dst, const void* src) {
    asm volatile("cp.async.cg.shared.global [%0], [%1], 16;" :: "r"(dst), "l"(src));
}
static __device__ __forceinline__ void mma_tf32(float& d0, float& d1, float& d2, float& d3,
                                                uint32_t a0, uint32_t a1, uint32_t a2, uint32_t a3,
                                                uint32_t b0, uint32_t b1) {
    asm volatile(
        "mma.sync.aligned.m16n8k8.row.col.f32.tf32.tf32.f32 "
        "{%0,%1,%2,%3}, {%4,%5,%6,%7}, {%8,%9}, {%0,%1,%2,%3};"
        : "+f"(d0), "+f"(d1), "+f"(d2), "+f"(d3)
        : "r"(a0), "r"(a1), "r"(a2), "r"(a3), "r"(b0), "r"(b1));
}

__global__ __launch_bounds__(256, 2)
void ssp_mma(const float* __restrict__ x,
             const float* __restrict__ W,
             const float* __restrict__ bias,
             const int*   __restrict__ sid,
             const int*   __restrict__ ccnt,
             const int*   __restrict__ slen_,
             float*       __restrict__ out)
{
    extern __shared__ float sm[];
    float* biasS = sm;                         // 128 floats
    float* Ws    = sm + 128;                   // 128 * WS_STR
    float* Xs    = Ws + TILE_S * WS_STR;       // 2 * XBUF

    const int tid  = threadIdx.x;
    const int lane = tid & 31;
    const int wid  = tid >> 5;
    const int lp   = lane >> 2;   // 0..7
    const int lq   = lane & 3;    // 0..3
    const int wsi  = wid >> 2;    // 0..1  (s)
    const int wti  = wid & 3;     // 0..3  (t)
    const int sb   = wsi * 64;
    const int tb   = wti * 32;

    const int b  = blockIdx.z;
    const int s0 = blockIdx.y * TILE_S;
    const int t0 = blockIdx.x * TILE_T;
    const int sl = slen_[b];

    float* outb = out + ((size_t)b * SS + s0) * TT + t0;

    // Fully masked tile: pure zero fill.
    if (t0 >= sl) {
        #pragma unroll 4
        for (int i = 0; i < 16; i++) {
            int idx = tid + i * 256;            // 0..4095 float4
            int row = idx >> 5, c4 = idx & 31;
            *(float4*)(outb + (size_t)row * TT + c4 * 4) = make_float4(0.f, 0.f, 0.f, 0.f);
        }
        return;
    }

    const int sess = sid[b];
    const int cc   = ccnt[b];
    const int nch  = (cc + 31) >> 5;           // 32-c chunks (2..4)

    if (tid < TILE_S) biasS[tid] = bias[sess * SS + s0 + tid];

    // --- Full W tile -> SMEM (tf32-rounded). 128x128 floats = 4096 float4. ---
    {
        const float* Wg = W + ((size_t)sess * SS + s0) * CMAX;
        #pragma unroll
        for (int i = 0; i < 16; i++) {
            int idx = tid + i * 256;
            int row = idx >> 5, c4 = idx & 31;
            float4 w4 = *(const float4*)(Wg + (size_t)row * CMAX + c4 * 4);
            float* d = Ws + row * WS_STR + c4 * 4;
            d[0] = __uint_as_float(f2tf32(w4.x));
            d[1] = __uint_as_float(f2tf32(w4.y));
            d[2] = __uint_as_float(f2tf32(w4.z));
            d[3] = __uint_as_float(f2tf32(w4.w));
        }
    }

    const float* xg = x + (size_t)b * CMAX * TT + t0;

    // Issue chunk 0 loads (32 rows x 128 floats = 1024 float4, 4/thread).
    {
        #pragma unroll
        for (int i = 0; i < 4; i++) {
            int idx = tid + i * 256;
            int k = idx >> 5, t4 = idx & 31;
            cp16(smem_u32(Xs + k * XS_STR + t4 * 4),
                 xg + (size_t)k * TT + t4 * 4);
        }
        asm volatile("cp.async.commit_group;" ::: "memory");
    }

    float acc[4][4][4];
    #pragma unroll
    for (int mt = 0; mt < 4; mt++)
        #pragma unroll
        for (int nt = 0; nt < 4; nt++)
            #pragma unroll
            for (int r = 0; r < 4; r++)
                acc[mt][nt][r] = 0.f;

    for (int q = 0; q < nch; q++) {
        if (q + 1 < nch) {
            float* dstb = Xs + ((q + 1) & 1) * XBUF;
            #pragma unroll
            for (int i = 0; i < 4; i++) {
                int idx = tid + i * 256;
                int k = idx >> 5, t4 = idx & 31;
                cp16(smem_u32(dstb + k * XS_STR + t4 * 4),
                     xg + (size_t)((q + 1) * 32 + k) * TT + t4 * 4);
            }
            asm volatile("cp.async.commit_group;" ::: "memory");
            asm volatile("cp.async.wait_group 1;" ::: "memory");
        } else {
            asm volatile("cp.async.wait_group 0;" ::: "memory");
        }
        __syncthreads();

        const float* Xb = Xs + (q & 1) * XBUF;
        const int kk0 = q * 32;

        #pragma unroll
        for (int k0 = 0; k0 < 32; k0 += 8) {
            // B fragments (x, k x t col-major), tf32-rounded at load
            uint32_t B0[4], B1[4];
            #pragma unroll
            for (int nt = 0; nt < 4; nt++) {
                int tcol = tb + nt * 8 + lp;
                B0[nt] = f2tf32(Xb[(k0 + lq) * XS_STR + tcol]);
                B1[nt] = f2tf32(Xb[(k0 + 4 + lq) * XS_STR + tcol]);
            }
            #pragma unroll
            for (int mt = 0; mt < 4; mt++) {
                const float* wr0 = Ws + (sb + mt * 16 + lp) * WS_STR + kk0 + k0 + lq;
                const float* wr1 = wr0 + 8 * WS_STR;
                uint32_t a0 = __float_as_uint(wr0[0]);
                uint32_t a1 = __float_as_uint(wr1[0]);
                uint32_t a2 = __float_as_uint(wr0[4]);
                uint32_t a3 = __float_as_uint(wr1[4]);
                #pragma unroll
                for (int nt = 0; nt < 4; nt++)
                    mma_tf32(acc[mt][nt][0], acc[mt][nt][1], acc[mt][nt][2], acc[mt][nt][3],
                             a0, a1, a2, a3, B0[nt], B1[nt]);
            }
        }
        __syncthreads();
    }

    // --- Epilogue: bias + seq mask, float2 stores along t ---
    #pragma unroll
    for (int mt = 0; mt < 4; mt++) {
        int sr = sb + mt * 16 + lp;
        float bs0 = biasS[sr];
        float bs1 = biasS[sr + 8];
        float* o0 = outb + (size_t)sr * TT;
        float* o1 = o0 + (size_t)8 * TT;
        #pragma unroll
        for (int nt = 0; nt < 4; nt++) {
            int tc = tb + nt * 8 + lq * 2;      // even -> 8B aligned
            bool m0 = (t0 + tc)     < sl;
            bool m1 = (t0 + tc + 1) < sl;
            float2 v0, v1;
            v0.x = m0 ? acc[mt][nt][0] + bs0 : 0.f;
            v0.y = m1 ? acc[mt][nt][1] + bs0 : 0.f;
            v1.x = m0 ? acc[mt][nt][2] + bs1 : 0.f;
            v1.y = m1 ? acc[mt][nt][3] + bs1 : 0.f;
            *(float2*)(o0 + tc) = v0;
            *(float2*)(o1 + tc) = v1;
        }
    }
}

extern "C" void kernel_launch(void* const* d_in, const int* in_sizes, int n_in,
                              void* d_out, int out_size)
{
    const float* x      = (const float*)d_in[0];
    const float* W      = (const float*)d_in[1];
    const float* bias   = (const float*)d_in[2];
    const int*   sid    = (const int*)d_in[3];
    const int*   ccount = (const int*)d_in[4];
    const int*   slen   = (const int*)d_in[5];
    float* out = (float*)d_out;

    const int smem_bytes = (128 + TILE_S * WS_STR + 2 * XBUF) * 4;   // ~103 KB
    cudaFuncSetAttribute(ssp_mma, cudaFuncAttributeMaxDynamicSharedMemorySize, smem_bytes);

    dim3 grid(TT / TILE_T, SS / TILE_S, BB);   // (32, 2, 64)
    ssp_mma<<<grid, 256, smem_bytes>>>(x, W, bias, sid, ccount, slen, out);
}